// round 9
// baseline (speedup 1.0000x reference)
#include <cuda_runtime.h>

// ============================================================================
// GraphSAGE 2-layer, mean aggregation.
//   Layer0: h = relu( mean_agg(x)@Wl0 + bl0 + x@Wr0 )
//   Layer1: out = mean_agg(h)@Wl1 + bl1 + h@Wr1
// Rewrite (aggregation is linear):
//   yl = x@Wl0 ; yr = x@Wr0 ; h = relu(agg(yl)/cnt + yr + bl0)
//   pq = h@[Wl1|Wr1] ; out = agg(p)/cnt + q + bl1
// Edge index dtype is detected at runtime (int32 vs int64 storage) and
// decoded once per call into an int2 scratch table.
// ============================================================================

#define NMAX 100000
#define EMAX 1600000

__device__ float g_YL  [NMAX * 128];
__device__ float g_YR  [NMAX * 128];
__device__ float g_AGG0[NMAX * 128];
__device__ float g_H   [NMAX * 128];
__device__ float g_PQ  [NMAX * 128];
__device__ float g_AGG1[NMAX * 64];
__device__ float g_CNT [NMAX];
__device__ float g_W1  [128 * 128];
__device__ int2  g_EDGE[EMAX];
__device__ int   g_FLAG;

typedef unsigned long long ull;

// ---------------- packed fp32x2 helpers (Blackwell FFMA2 pipe) ----------------
__device__ __forceinline__ ull pack2(float v) {
    ull r; unsigned u = __float_as_uint(v);
    asm("mov.b64 %0, {%1, %2};" : "=l"(r) : "r"(u), "r"(u));
    return r;
}
__device__ __forceinline__ ull fma2(ull a, ull b, ull c) {
    ull d;
    asm("fma.rn.f32x2 %0, %1, %2, %3;" : "=l"(d) : "l"(a), "l"(b), "l"(c));
    return d;
}
__device__ __forceinline__ void unpack2(ull v, float& lo, float& hi) {
    unsigned ulo, uhi;
    asm("mov.b64 {%0, %1}, %2;" : "=r"(ulo), "=r"(uhi) : "l"(v));
    lo = __uint_as_float(ulo); hi = __uint_as_float(uhi);
}

// ============================================================================
// Edge dtype detection + decode (+ fused in-degree count).
// ============================================================================

// Under int64 little-endian storage with indices in [0, 100000), every odd
// int32 word of the buffer is zero. Under int32 storage odd words are random
// node ids. 128 odd words all zero => int64.
__global__ void detect_kernel(const int* __restrict__ raw, int nwords, int* flag) {
    if (blockIdx.x == 0 && threadIdx.x == 0) {
        int is64 = 1;
        int lim = nwords < 256 ? nwords : 256;
        for (int i = 1; i < lim; i += 2)
            if (raw[i] != 0) { is64 = 0; break; }
        *flag = is64;
    }
}

__global__ void decode_edges(const void* __restrict__ eiraw, int E, int N,
                             const int* __restrict__ flag,
                             int2* __restrict__ edge,
                             float* __restrict__ cnt)
{
    int e = blockIdx.x * blockDim.x + threadIdx.x;
    if (e >= E) return;
    int s, d;
    if (*flag) {
        const long long* p = (const long long*)eiraw;
        s = (int)p[e];
        d = (int)p[(size_t)E + e];
    } else {
        const int* p = (const int*)eiraw;
        s = p[e];
        d = p[(size_t)E + e];
    }
    // clamp defensively: a wrong dtype guess shows up as rel_err, not a crash
    s = min(max(s, 0), N - 1);
    d = min(max(d, 0), N - 1);
    edge[e] = make_int2(s, d);
    atomicAdd(&cnt[d], 1.0f);
}

// ============================================================================
// GEMM: C[nrows,128] = A[nrows,128] @ B[128,128], fp32, FFMA2 inner loop.
// BM=128, BN=128, BK=16, 256 threads; thread tile 8x8 (4 row-pairs x 8 cols).
// ============================================================================
__global__ __launch_bounds__(256) void gemm128(
    const float* __restrict__ A, const float* __restrict__ B,
    float* __restrict__ C, int nrows)
{
    __shared__ float As[16][132];   // [k][m], padded
    __shared__ float Bs[16][128];   // [k][n]

    const int t    = threadIdx.x;
    const int tx   = t & 15;        // n-group (8 cols each)
    const int ty   = t >> 4;        // m-group (8 rows each)
    const int row0 = blockIdx.x * 128;

    ull acc[4][8];
#pragma unroll
    for (int p = 0; p < 4; p++)
#pragma unroll
        for (int n = 0; n < 8; n++) acc[p][n] = 0ull;

    for (int k0 = 0; k0 < 128; k0 += 16) {
        // A tile 128x16, transposed into As[k][m]; 2 float4 per thread
#pragma unroll
        for (int i = 0; i < 2; i++) {
            int f = t + i * 256;
            int r = f >> 2, kq = (f & 3) << 2;
            float4 v = make_float4(0.f, 0.f, 0.f, 0.f);
            if (row0 + r < nrows)
                v = *(const float4*)&A[(size_t)(row0 + r) * 128 + k0 + kq];
            As[kq + 0][r] = v.x; As[kq + 1][r] = v.y;
            As[kq + 2][r] = v.z; As[kq + 3][r] = v.w;
        }
        // B tile 16x128; 2 float4 per thread, contiguous
#pragma unroll
        for (int i = 0; i < 2; i++) {
            int f = t + i * 256;
            int kk = f >> 5, c = (f & 31) << 2;
            *(float4*)&Bs[kk][c] = *(const float4*)&B[(size_t)(k0 + kk) * 128 + c];
        }
        __syncthreads();

#pragma unroll
        for (int kk = 0; kk < 16; kk++) {
            ull a2[4];
            const ull* pa = (const ull*)&As[kk][ty * 8];
#pragma unroll
            for (int p = 0; p < 4; p++) a2[p] = pa[p];
            float4 b0 = *(const float4*)&Bs[kk][tx * 8];
            float4 b1 = *(const float4*)&Bs[kk][tx * 8 + 4];
            ull b2[8];
            b2[0] = pack2(b0.x); b2[1] = pack2(b0.y);
            b2[2] = pack2(b0.z); b2[3] = pack2(b0.w);
            b2[4] = pack2(b1.x); b2[5] = pack2(b1.y);
            b2[6] = pack2(b1.z); b2[7] = pack2(b1.w);
#pragma unroll
            for (int p = 0; p < 4; p++)
#pragma unroll
                for (int n = 0; n < 8; n++)
                    acc[p][n] = fma2(a2[p], b2[n], acc[p][n]);
        }
        __syncthreads();
    }

#pragma unroll
    for (int p = 0; p < 4; p++) {
        int r = row0 + ty * 8 + 2 * p;
        float lo[8], hi[8];
#pragma unroll
        for (int n = 0; n < 8; n++) unpack2(acc[p][n], lo[n], hi[n]);
        if (r < nrows) {
            *(float4*)&C[(size_t)r * 128 + tx * 8]     = make_float4(lo[0], lo[1], lo[2], lo[3]);
            *(float4*)&C[(size_t)r * 128 + tx * 8 + 4] = make_float4(lo[4], lo[5], lo[6], lo[7]);
        }
        if (r + 1 < nrows) {
            *(float4*)&C[(size_t)(r + 1) * 128 + tx * 8]     = make_float4(hi[0], hi[1], hi[2], hi[3]);
            *(float4*)&C[(size_t)(r + 1) * 128 + tx * 8 + 4] = make_float4(hi[4], hi[5], hi[6], hi[7]);
        }
    }
}

// ============================================================================
// Helper kernels
// ============================================================================
__global__ void zero_kernel(float4* __restrict__ p, int n4) {
    int i = blockIdx.x * blockDim.x + threadIdx.x;
    if (i < n4) p[i] = make_float4(0.f, 0.f, 0.f, 0.f);
}

__global__ void concat_w1(const float* __restrict__ Wl1,
                          const float* __restrict__ Wr1,
                          float* __restrict__ W1) {
    int i = blockIdx.x * blockDim.x + threadIdx.x;
    if (i >= 128 * 128) return;
    int k = i >> 7, n = i & 127;
    W1[i] = (n < 64) ? Wl1[k * 64 + n] : Wr1[k * 64 + n - 64];
}

// Scatter-add: VPR float4 lanes per edge. Gather src row, vector-RED into dst row.
template<int VPR>
__global__ void scatter_kernel(const int2* __restrict__ edge, int E,
                               const float* __restrict__ srcbuf, int sstride,
                               float* __restrict__ agg, int dstride)
{
    int g = blockIdx.x * blockDim.x + threadIdx.x;
    int e = g / VPR;
    if (e >= E) return;
    int lane = g % VPR;
    int2 sd = edge[e];                 // broadcast within the VPR group
    float4 v = *(const float4*)&srcbuf[(size_t)sd.x * sstride + lane * 4];
    const float* dp = &agg[(size_t)sd.y * dstride + lane * 4];
    ull ga = (ull)__cvta_generic_to_global((void*)dp);
    asm volatile("red.global.add.v4.f32 [%0], {%1, %2, %3, %4};"
                 :: "l"(ga), "f"(v.x), "f"(v.y), "f"(v.z), "f"(v.w) : "memory");
}

// h = relu(agg/max(cnt,1) + yr + bias), 128 cols
__global__ void combine_relu(const float* __restrict__ agg,
                             const float* __restrict__ yr,
                             const float* __restrict__ cnt,
                             const float* __restrict__ bias,
                             float* __restrict__ h, int n)
{
    int g = blockIdx.x * blockDim.x + threadIdx.x;
    if (g >= n * 32) return;
    int row = g >> 5, c = (g & 31) << 2;
    float inv = 1.0f / fmaxf(cnt[row], 1.0f);
    float4 a = *(const float4*)&agg[(size_t)row * 128 + c];
    float4 y = *(const float4*)&yr [(size_t)row * 128 + c];
    float4 b = *(const float4*)&bias[c];
    float4 o;
    o.x = fmaxf(fmaf(a.x, inv, y.x + b.x), 0.f);
    o.y = fmaxf(fmaf(a.y, inv, y.y + b.y), 0.f);
    o.z = fmaxf(fmaf(a.z, inv, y.z + b.z), 0.f);
    o.w = fmaxf(fmaf(a.w, inv, y.w + b.w), 0.f);
    *(float4*)&h[(size_t)row * 128 + c] = o;
}

// out = agg/max(cnt,1) + q + bias, 64 cols (q = pq cols 64..127)
__global__ void combine_out(const float* __restrict__ agg,
                            const float* __restrict__ pq,
                            const float* __restrict__ cnt,
                            const float* __restrict__ bias,
                            float* __restrict__ out, int n)
{
    int g = blockIdx.x * blockDim.x + threadIdx.x;
    if (g >= n * 16) return;
    int row = g >> 4, c = (g & 15) << 2;
    float inv = 1.0f / fmaxf(cnt[row], 1.0f);
    float4 a = *(const float4*)&agg[(size_t)row * 64 + c];
    float4 q = *(const float4*)&pq [(size_t)row * 128 + 64 + c];
    float4 b = *(const float4*)&bias[c];
    float4 o;
    o.x = fmaf(a.x, inv, q.x + b.x);
    o.y = fmaf(a.y, inv, q.y + b.y);
    o.z = fmaf(a.z, inv, q.z + b.z);
    o.w = fmaf(a.w, inv, q.w + b.w);
    *(float4*)&out[(size_t)row * 64 + c] = o;
}

// ============================================================================
// kernel_launch — graph-capturable, allocation-free, deterministic per call.
// ============================================================================
extern "C" void kernel_launch(void* const* d_in, const int* in_sizes, int n_in,
                              void* d_out, int out_size)
{
    const float* x   = (const float*)d_in[0];
    const void*  ei  = d_in[1];                    // int32 or int64 — detected on device
    const float* Wl0 = (const float*)d_in[2];
    const float* bl0 = (const float*)d_in[3];
    const float* Wr0 = (const float*)d_in[4];
    const float* Wl1 = (const float*)d_in[5];
    const float* bl1 = (const float*)d_in[6];
    const float* Wr1 = (const float*)d_in[7];
    float*       out = (float*)d_out;

    const int N = in_sizes[0] / 128;   // 100000
    const int E = in_sizes[1] / 2;     // 1600000

    float *YL, *YR, *AGG0, *H, *PQ, *AGG1, *CNT, *W1;
    int2* EDGE; int* FLAG;
    cudaGetSymbolAddress((void**)&YL,   g_YL);
    cudaGetSymbolAddress((void**)&YR,   g_YR);
    cudaGetSymbolAddress((void**)&AGG0, g_AGG0);
    cudaGetSymbolAddress((void**)&H,    g_H);
    cudaGetSymbolAddress((void**)&PQ,   g_PQ);
    cudaGetSymbolAddress((void**)&AGG1, g_AGG1);
    cudaGetSymbolAddress((void**)&CNT,  g_CNT);
    cudaGetSymbolAddress((void**)&W1,   g_W1);
    cudaGetSymbolAddress((void**)&EDGE, g_EDGE);
    cudaGetSymbolAddress((void**)&FLAG, g_FLAG);

    const int TPB = 256;

    // zero accumulators + counts (every call: replay-safe)
    zero_kernel<<<(N * 32 + TPB - 1) / TPB, TPB>>>((float4*)AGG0, N * 32);
    zero_kernel<<<(N * 16 + TPB - 1) / TPB, TPB>>>((float4*)AGG1, N * 16);
    zero_kernel<<<(N / 4 + TPB - 1) / TPB, TPB>>>((float4*)CNT,  N / 4);

    // edge dtype detection + decode + in-degree count
    detect_kernel<<<1, 32>>>((const int*)ei, in_sizes[1], FLAG);
    decode_edges<<<(E + TPB - 1) / TPB, TPB>>>(ei, E, N, FLAG, EDGE, CNT);

    // W1cat = [Wl1 | Wr1]  (128 x 128)
    concat_w1<<<(128 * 128 + TPB - 1) / TPB, TPB>>>(Wl1, Wr1, W1);

    // Layer 0 GEMMs: yl = x@Wl0, yr = x@Wr0
    gemm128<<<(N + 127) / 128, 256>>>(x, Wl0, YL, N);
    gemm128<<<(N + 127) / 128, 256>>>(x, Wr0, YR, N);

    // Layer 0 scatter: AGG0[dst] += yl[src]   (128 f32 = 32 vec4 lanes/edge)
    {
        long long tot = (long long)E * 32;
        scatter_kernel<32><<<(unsigned)((tot + TPB - 1) / TPB), TPB>>>(
            EDGE, E, YL, 128, AGG0, 128);
    }

    // h = relu(AGG0/cnt + yr + bl0)
    combine_relu<<<(N * 32 + TPB - 1) / TPB, TPB>>>(AGG0, YR, CNT, bl0, H, N);

    // Layer 1 GEMM: pq = h @ [Wl1|Wr1]   (p = cols 0..63, q = cols 64..127)
    gemm128<<<(N + 127) / 128, 256>>>(H, W1, PQ, N);

    // Layer 1 scatter: AGG1[dst] += p[src]   (64 f32 = 16 vec4 lanes/edge)
    {
        long long tot = (long long)E * 16;
        scatter_kernel<16><<<(unsigned)((tot + TPB - 1) / TPB), TPB>>>(
            EDGE, E, PQ, 128, AGG1, 64);
    }

    // out = AGG1/cnt + q + bl1
    combine_out<<<(N * 16 + TPB - 1) / TPB, TPB>>>(AGG1, PQ, CNT, bl1, out, N);
}

// round 10
// speedup vs baseline: 1.5454x; 1.5454x over previous
#include <cuda_runtime.h>

// ============================================================================
// GraphSAGE 2-layer, mean aggregation. CSR gather-reduce formulation:
//   yl = x@Wl0 ; yr = x@Wr0          (one dual-output GEMM)
//   CSR = sort edges by dst (histogram + scan + fill, rebuilt per call)
//   h   = relu( (sum_{s in N(d)} yl[s]) / max(deg,1) + yr + bl0 )   (fused)
//   pq  = h@[Wl1|Wr1]
//   out = (sum p[s]) / max(deg,1) + q + bl1                          (fused)
// No float atomics anywhere; aggregation reads are L2-resident gathers.
// ============================================================================

#define NMAX 100000
#define EMAX 1600000
#define SCAN_B 1024
#define NBLK ((NMAX + SCAN_B - 1) / SCAN_B)

__device__ float g_YL  [NMAX * 128];
__device__ float g_YR  [NMAX * 128];
__device__ float g_H   [NMAX * 128];
__device__ float g_PQ  [NMAX * 128];
__device__ float g_W1  [128 * 128];
__device__ int2  g_EDGE[EMAX];
__device__ int   g_SRC [EMAX];
__device__ int   g_DEG [NMAX];
__device__ int   g_OFF [NMAX];
__device__ int   g_CUR [NMAX];
__device__ int   g_BSUM[NBLK];
__device__ int   g_FLAG;

typedef unsigned long long ull;

// ---------------- packed fp32x2 helpers (Blackwell FFMA2 pipe) ----------------
__device__ __forceinline__ ull pack2(float v) {
    ull r; unsigned u = __float_as_uint(v);
    asm("mov.b64 %0, {%1, %2};" : "=l"(r) : "r"(u), "r"(u));
    return r;
}
__device__ __forceinline__ ull fma2(ull a, ull b, ull c) {
    ull d;
    asm("fma.rn.f32x2 %0, %1, %2, %3;" : "=l"(d) : "l"(a), "l"(b), "l"(c));
    return d;
}
__device__ __forceinline__ void unpack2(ull v, float& lo, float& hi) {
    unsigned ulo, uhi;
    asm("mov.b64 {%0, %1}, %2;" : "=r"(ulo), "=r"(uhi) : "l"(v));
    lo = __uint_as_float(ulo); hi = __uint_as_float(uhi);
}

// ============================================================================
// Edge dtype detection + decode + degree histogram
// ============================================================================
__global__ void detect_kernel(const int* __restrict__ raw, int nwords, int* flag) {
    if (blockIdx.x == 0 && threadIdx.x == 0) {
        int is64 = 1;
        int lim = nwords < 256 ? nwords : 256;
        for (int i = 1; i < lim; i += 2)
            if (raw[i] != 0) { is64 = 0; break; }
        *flag = is64;
    }
}

__global__ void zero_int(int* __restrict__ p, int n) {
    int i = blockIdx.x * blockDim.x + threadIdx.x;
    if (i < n) p[i] = 0;
}

__global__ void decode_edges(const void* __restrict__ eiraw, int E, int N,
                             const int* __restrict__ flag,
                             int2* __restrict__ edge, int* __restrict__ deg)
{
    int e = blockIdx.x * blockDim.x + threadIdx.x;
    if (e >= E) return;
    int s, d;
    if (*flag) {
        const long long* p = (const long long*)eiraw;
        s = (int)p[e];
        d = (int)p[(size_t)E + e];
    } else {
        const int* p = (const int*)eiraw;
        s = p[e];
        d = p[(size_t)E + e];
    }
    s = min(max(s, 0), N - 1);
    d = min(max(d, 0), N - 1);
    edge[e] = make_int2(s, d);
    atomicAdd(&deg[d], 1);
}

// ============================================================================
// Exclusive scan over degrees (3 kernels) + CSR fill
// ============================================================================
__global__ __launch_bounds__(SCAN_B) void scan1(
    const int* __restrict__ deg, int N,
    int* __restrict__ excl, int* __restrict__ bsum)
{
    __shared__ int sh[SCAN_B];
    int gid = blockIdx.x * SCAN_B + threadIdx.x;
    int v = (gid < N) ? deg[gid] : 0;
    sh[threadIdx.x] = v;
    __syncthreads();
#pragma unroll
    for (int off = 1; off < SCAN_B; off <<= 1) {
        int t = (threadIdx.x >= off) ? sh[threadIdx.x - off] : 0;
        __syncthreads();
        sh[threadIdx.x] += t;
        __syncthreads();
    }
    if (gid < N) excl[gid] = sh[threadIdx.x] - v;
    if (threadIdx.x == SCAN_B - 1) bsum[blockIdx.x] = sh[SCAN_B - 1];
}

__global__ void scan2(int* __restrict__ bsum, int nb) {
    if (blockIdx.x == 0 && threadIdx.x == 0) {
        int acc = 0;
        for (int i = 0; i < nb; i++) { int v = bsum[i]; bsum[i] = acc; acc += v; }
    }
}

__global__ void scan3(int* __restrict__ off, const int* __restrict__ bsum,
                      int N, int* __restrict__ cur)
{
    int gid = blockIdx.x * blockDim.x + threadIdx.x;
    if (gid < N) {
        int o = off[gid] + bsum[gid >> 10];
        off[gid] = o;
        cur[gid] = o;
    }
}

__global__ void fill_csr(const int2* __restrict__ edge, int E,
                         int* __restrict__ cur, int* __restrict__ srcarr)
{
    int e = blockIdx.x * blockDim.x + threadIdx.x;
    if (e >= E) return;
    int2 sd = edge[e];
    int slot = atomicAdd(&cur[sd.y], 1);
    srcarr[slot] = sd.x;
}

// ============================================================================
// Dual-output GEMM: C{0,1}[nrows,128] = A[nrows,128] @ B{0,1}[128,128].
// blockIdx.y selects the (B,C) pair. FFMA2 inner loop, 8x8 thread tiles.
// ============================================================================
__global__ __launch_bounds__(256) void gemm128d(
    const float* __restrict__ A,
    const float* __restrict__ B0, float* __restrict__ C0,
    const float* __restrict__ B1, float* __restrict__ C1,
    int nrows)
{
    __shared__ float As[16][132];
    __shared__ float Bs[16][128];

    const float* B = blockIdx.y ? B1 : B0;
    float*       C = blockIdx.y ? C1 : C0;

    const int t    = threadIdx.x;
    const int tx   = t & 15;
    const int ty   = t >> 4;
    const int row0 = blockIdx.x * 128;

    ull acc[4][8];
#pragma unroll
    for (int p = 0; p < 4; p++)
#pragma unroll
        for (int n = 0; n < 8; n++) acc[p][n] = 0ull;

    for (int k0 = 0; k0 < 128; k0 += 16) {
#pragma unroll
        for (int i = 0; i < 2; i++) {
            int f = t + i * 256;
            int r = f >> 2, kq = (f & 3) << 2;
            float4 v = make_float4(0.f, 0.f, 0.f, 0.f);
            if (row0 + r < nrows)
                v = *(const float4*)&A[(size_t)(row0 + r) * 128 + k0 + kq];
            As[kq + 0][r] = v.x; As[kq + 1][r] = v.y;
            As[kq + 2][r] = v.z; As[kq + 3][r] = v.w;
        }
#pragma unroll
        for (int i = 0; i < 2; i++) {
            int f = t + i * 256;
            int kk = f >> 5, c = (f & 31) << 2;
            *(float4*)&Bs[kk][c] = *(const float4*)&B[(size_t)(k0 + kk) * 128 + c];
        }
        __syncthreads();

#pragma unroll
        for (int kk = 0; kk < 16; kk++) {
            ull a2[4];
            const ull* pa = (const ull*)&As[kk][ty * 8];
#pragma unroll
            for (int p = 0; p < 4; p++) a2[p] = pa[p];
            float4 b0 = *(const float4*)&Bs[kk][tx * 8];
            float4 b1 = *(const float4*)&Bs[kk][tx * 8 + 4];
            ull b2[8];
            b2[0] = pack2(b0.x); b2[1] = pack2(b0.y);
            b2[2] = pack2(b0.z); b2[3] = pack2(b0.w);
            b2[4] = pack2(b1.x); b2[5] = pack2(b1.y);
            b2[6] = pack2(b1.z); b2[7] = pack2(b1.w);
#pragma unroll
            for (int p = 0; p < 4; p++)
#pragma unroll
                for (int n = 0; n < 8; n++)
                    acc[p][n] = fma2(a2[p], b2[n], acc[p][n]);
        }
        __syncthreads();
    }

#pragma unroll
    for (int p = 0; p < 4; p++) {
        int r = row0 + ty * 8 + 2 * p;
        float lo[8], hi[8];
#pragma unroll
        for (int n = 0; n < 8; n++) unpack2(acc[p][n], lo[n], hi[n]);
        if (r < nrows) {
            *(float4*)&C[(size_t)r * 128 + tx * 8]     = make_float4(lo[0], lo[1], lo[2], lo[3]);
            *(float4*)&C[(size_t)r * 128 + tx * 8 + 4] = make_float4(lo[4], lo[5], lo[6], lo[7]);
        }
        if (r + 1 < nrows) {
            *(float4*)&C[(size_t)(r + 1) * 128 + tx * 8]     = make_float4(hi[0], hi[1], hi[2], hi[3]);
            *(float4*)&C[(size_t)(r + 1) * 128 + tx * 8 + 4] = make_float4(hi[4], hi[5], hi[6], hi[7]);
        }
    }
}

__global__ void concat_w1(const float* __restrict__ Wl1,
                          const float* __restrict__ Wr1,
                          float* __restrict__ W1) {
    int i = blockIdx.x * blockDim.x + threadIdx.x;
    if (i >= 128 * 128) return;
    int k = i >> 7, n = i & 127;
    W1[i] = (n < 64) ? Wl1[k * 64 + n] : Wr1[k * 64 + n - 64];
}

// ============================================================================
// Fused CSR gather-reduce + combine. One warp per destination row.
// Layer0 (128 cols, float4/lane): h = relu(sum/deg + yr + bl0)
// ============================================================================
__global__ __launch_bounds__(256) void agg_combine_relu(
    const int* __restrict__ off, const int* __restrict__ deg,
    const int* __restrict__ srcarr,
    const float* __restrict__ YL, const float* __restrict__ YR,
    const float* __restrict__ bias,
    float* __restrict__ H, int n)
{
    int warp = (blockIdx.x * 256 + threadIdx.x) >> 5;
    int lane = threadIdx.x & 31;
    if (warp >= n) return;
    int start = off[warp], len = deg[warp];
    int c = lane << 2;

    float4 acc = make_float4(0.f, 0.f, 0.f, 0.f);
    int j = 0;
    for (; j + 4 <= len; j += 4) {
        int s0 = __ldg(&srcarr[start + j + 0]);
        int s1 = __ldg(&srcarr[start + j + 1]);
        int s2 = __ldg(&srcarr[start + j + 2]);
        int s3 = __ldg(&srcarr[start + j + 3]);
        float4 v0 = __ldg((const float4*)&YL[(size_t)s0 * 128 + c]);
        float4 v1 = __ldg((const float4*)&YL[(size_t)s1 * 128 + c]);
        float4 v2 = __ldg((const float4*)&YL[(size_t)s2 * 128 + c]);
        float4 v3 = __ldg((const float4*)&YL[(size_t)s3 * 128 + c]);
        acc.x += (v0.x + v1.x) + (v2.x + v3.x);
        acc.y += (v0.y + v1.y) + (v2.y + v3.y);
        acc.z += (v0.z + v1.z) + (v2.z + v3.z);
        acc.w += (v0.w + v1.w) + (v2.w + v3.w);
    }
    for (; j < len; j++) {
        int s = __ldg(&srcarr[start + j]);
        float4 v = __ldg((const float4*)&YL[(size_t)s * 128 + c]);
        acc.x += v.x; acc.y += v.y; acc.z += v.z; acc.w += v.w;
    }

    float inv = 1.0f / fmaxf((float)len, 1.0f);
    float4 y = *(const float4*)&YR[(size_t)warp * 128 + c];
    float4 b = *(const float4*)&bias[c];
    float4 o;
    o.x = fmaxf(fmaf(acc.x, inv, y.x + b.x), 0.f);
    o.y = fmaxf(fmaf(acc.y, inv, y.y + b.y), 0.f);
    o.z = fmaxf(fmaf(acc.z, inv, y.z + b.z), 0.f);
    o.w = fmaxf(fmaf(acc.w, inv, y.w + b.w), 0.f);
    *(float4*)&H[(size_t)warp * 128 + c] = o;
}

// Layer1 (64 agg cols, float2/lane): out = sum(p)/deg + q + bl1
__global__ __launch_bounds__(256) void agg_combine_out(
    const int* __restrict__ off, const int* __restrict__ deg,
    const int* __restrict__ srcarr,
    const float* __restrict__ PQ, const float* __restrict__ bias,
    float* __restrict__ out, int n)
{
    int warp = (blockIdx.x * 256 + threadIdx.x) >> 5;
    int lane = threadIdx.x & 31;
    if (warp >= n) return;
    int start = off[warp], len = deg[warp];
    int c = lane << 1;

    float2 acc = make_float2(0.f, 0.f);
    int j = 0;
    for (; j + 4 <= len; j += 4) {
        int s0 = __ldg(&srcarr[start + j + 0]);
        int s1 = __ldg(&srcarr[start + j + 1]);
        int s2 = __ldg(&srcarr[start + j + 2]);
        int s3 = __ldg(&srcarr[start + j + 3]);
        float2 v0 = __ldg((const float2*)&PQ[(size_t)s0 * 128 + c]);
        float2 v1 = __ldg((const float2*)&PQ[(size_t)s1 * 128 + c]);
        float2 v2 = __ldg((const float2*)&PQ[(size_t)s2 * 128 + c]);
        float2 v3 = __ldg((const float2*)&PQ[(size_t)s3 * 128 + c]);
        acc.x += (v0.x + v1.x) + (v2.x + v3.x);
        acc.y += (v0.y + v1.y) + (v2.y + v3.y);
    }
    for (; j < len; j++) {
        int s = __ldg(&srcarr[start + j]);
        float2 v = __ldg((const float2*)&PQ[(size_t)s * 128 + c]);
        acc.x += v.x; acc.y += v.y;
    }

    float inv = 1.0f / fmaxf((float)len, 1.0f);
    float2 q = *(const float2*)&PQ[(size_t)warp * 128 + 64 + c];
    float2 b = *(const float2*)&bias[c];
    float2 o;
    o.x = fmaf(acc.x, inv, q.x + b.x);
    o.y = fmaf(acc.y, inv, q.y + b.y);
    *(float2*)&out[(size_t)warp * 64 + c] = o;
}

// ============================================================================
// kernel_launch — graph-capturable, allocation-free, deterministic per call.
// ============================================================================
extern "C" void kernel_launch(void* const* d_in, const int* in_sizes, int n_in,
                              void* d_out, int out_size)
{
    const float* x   = (const float*)d_in[0];
    const void*  ei  = d_in[1];
    const float* Wl0 = (const float*)d_in[2];
    const float* bl0 = (const float*)d_in[3];
    const float* Wr0 = (const float*)d_in[4];
    const float* Wl1 = (const float*)d_in[5];
    const float* bl1 = (const float*)d_in[6];
    const float* Wr1 = (const float*)d_in[7];
    float*       out = (float*)d_out;

    const int N = in_sizes[0] / 128;   // 100000
    const int E = in_sizes[1] / 2;     // 1600000

    float *YL, *YR, *H, *PQ, *W1;
    int2* EDGE; int *SRC, *DEG, *OFF, *CUR, *BSUM, *FLAG;
    cudaGetSymbolAddress((void**)&YL,   g_YL);
    cudaGetSymbolAddress((void**)&YR,   g_YR);
    cudaGetSymbolAddress((void**)&H,    g_H);
    cudaGetSymbolAddress((void**)&PQ,   g_PQ);
    cudaGetSymbolAddress((void**)&W1,   g_W1);
    cudaGetSymbolAddress((void**)&EDGE, g_EDGE);
    cudaGetSymbolAddress((void**)&SRC,  g_SRC);
    cudaGetSymbolAddress((void**)&DEG,  g_DEG);
    cudaGetSymbolAddress((void**)&OFF,  g_OFF);
    cudaGetSymbolAddress((void**)&CUR,  g_CUR);
    cudaGetSymbolAddress((void**)&BSUM, g_BSUM);
    cudaGetSymbolAddress((void**)&FLAG, g_FLAG);

    const int TPB = 256;
    const int nScanBlk = (N + SCAN_B - 1) / SCAN_B;

    // ---- edge preprocessing ----
    zero_int<<<(N + TPB - 1) / TPB, TPB>>>(DEG, N);
    detect_kernel<<<1, 32>>>((const int*)ei, in_sizes[1], FLAG);
    decode_edges<<<(E + TPB - 1) / TPB, TPB>>>(ei, E, N, FLAG, EDGE, DEG);

    // ---- layer 0 GEMMs (independent of CSR; heavy launch early) ----
    {
        dim3 grid((N + 127) / 128, 2);
        gemm128d<<<grid, 256>>>(x, Wl0, YL, Wr0, YR, N);
    }

    // ---- CSR build: exclusive scan + fill ----
    scan1<<<nScanBlk, SCAN_B>>>(DEG, N, OFF, BSUM);
    scan2<<<1, 32>>>(BSUM, nScanBlk);
    scan3<<<(N + TPB - 1) / TPB, TPB>>>(OFF, BSUM, N, CUR);
    fill_csr<<<(E + TPB - 1) / TPB, TPB>>>(EDGE, E, CUR, SRC);

    // ---- W1cat = [Wl1 | Wr1] ----
    concat_w1<<<(128 * 128 + TPB - 1) / TPB, TPB>>>(Wl1, Wr1, W1);

    // ---- layer 0 aggregation + combine + relu (fused) ----
    agg_combine_relu<<<(N * 32 + TPB - 1) / TPB, TPB>>>(
        OFF, DEG, SRC, YL, YR, bl0, H, N);

    // ---- layer 1 GEMM: pq = h @ [Wl1|Wr1] ----
    {
        dim3 grid((N + 127) / 128, 1);
        gemm128d<<<grid, 256>>>(H, W1, PQ, W1, PQ, N);
    }

    // ---- layer 1 aggregation + combine (fused) -> out ----
    agg_combine_out<<<(N * 32 + TPB - 1) / TPB, TPB>>>(
        OFF, DEG, SRC, PQ, bl1, out, N);
}

// round 12
// speedup vs baseline: 2.3833x; 1.5422x over previous
#include <cuda_runtime.h>
#include <cstdint>

// ============================================================================
// GraphSAGE 2-layer, mean aggregation. CSR gather-reduce + tf32 mma.sync GEMMs
// (base-ISA tensor path: harness compiles to target sm_103, no tcgen05).
//   yl,yr = x@Wl0, x@Wr0      (one launch, blockIdx.y selects weight/output)
//   h     = relu(agg(yl)/deg + yr + bl0)          (fused CSR gather)
//   pq    = h@[Wl1|Wr1]                           (tensor-core)
//   out   = agg(p)/deg + q + bl1                  (fused CSR gather)
// ============================================================================

#define NMAX 100000
#define EMAX 1600000
#define SCAN_B 1024
#define NBLK ((NMAX + SCAN_B - 1) / SCAN_B)

__device__ float g_YL [NMAX * 128];
__device__ float g_YR [NMAX * 128];
__device__ float g_H  [NMAX * 128];
__device__ float g_PQ [NMAX * 128];
__device__ float g_WT0[256 * 128];   // [n][k] tf32-rounded; n<128: Wl0^T, else Wr0^T
__device__ float g_WT1[128 * 128];   // [n][k] tf32-rounded; n<64: Wl1^T, else Wr1^T
__device__ int2  g_EDGE[EMAX];
__device__ int   g_SRC [EMAX];
__device__ int   g_DEG [NMAX];
__device__ int   g_OFF [NMAX];
__device__ int   g_CUR [NMAX];
__device__ int   g_BSUM[NBLK];
__device__ int   g_FLAG;

__device__ __forceinline__ uint32_t f2tf32(float v) {
    uint32_t t; asm("cvt.rna.tf32.f32 %0, %1;" : "=r"(t) : "f"(v)); return t;
}
__device__ __forceinline__ void mma_tf32(float* c, const uint32_t* a,
                                         uint32_t b0, uint32_t b1) {
    asm volatile(
        "mma.sync.aligned.m16n8k8.row.col.f32.tf32.tf32.f32 "
        "{%0,%1,%2,%3}, {%4,%5,%6,%7}, {%8,%9}, {%0,%1,%2,%3};"
        : "+f"(c[0]), "+f"(c[1]), "+f"(c[2]), "+f"(c[3])
        : "r"(a[0]), "r"(a[1]), "r"(a[2]), "r"(a[3]), "r"(b0), "r"(b1));
}

// ============================================================================
// Edge preprocessing (detect dtype, decode, histogram, scan, CSR fill)
// ============================================================================
__global__ void detect_kernel(const int* __restrict__ raw, int nwords, int* flag) {
    if (blockIdx.x == 0 && threadIdx.x == 0) {
        int is64 = 1;
        int lim = nwords < 256 ? nwords : 256;
        for (int i = 1; i < lim; i += 2)
            if (raw[i] != 0) { is64 = 0; break; }
        *flag = is64;
    }
}
__global__ void zero_int(int* __restrict__ p, int n) {
    int i = blockIdx.x * blockDim.x + threadIdx.x;
    if (i < n) p[i] = 0;
}
__global__ void decode_edges(const void* __restrict__ eiraw, int E, int N,
                             const int* __restrict__ flag,
                             int2* __restrict__ edge, int* __restrict__ deg)
{
    int e = blockIdx.x * blockDim.x + threadIdx.x;
    if (e >= E) return;
    int s, d;
    if (*flag) {
        const long long* p = (const long long*)eiraw;
        s = (int)p[e]; d = (int)p[(size_t)E + e];
    } else {
        const int* p = (const int*)eiraw;
        s = p[e]; d = p[(size_t)E + e];
    }
    s = min(max(s, 0), N - 1);
    d = min(max(d, 0), N - 1);
    edge[e] = make_int2(s, d);
    atomicAdd(&deg[d], 1);
}
__global__ __launch_bounds__(SCAN_B) void scan1(
    const int* __restrict__ deg, int N, int* __restrict__ excl, int* __restrict__ bsum)
{
    __shared__ int sh[SCAN_B];
    int gid = blockIdx.x * SCAN_B + threadIdx.x;
    int v = (gid < N) ? deg[gid] : 0;
    sh[threadIdx.x] = v;
    __syncthreads();
#pragma unroll
    for (int off = 1; off < SCAN_B; off <<= 1) {
        int t = (threadIdx.x >= off) ? sh[threadIdx.x - off] : 0;
        __syncthreads();
        sh[threadIdx.x] += t;
        __syncthreads();
    }
    if (gid < N) excl[gid] = sh[threadIdx.x] - v;
    if (threadIdx.x == SCAN_B - 1) bsum[blockIdx.x] = sh[SCAN_B - 1];
}
__global__ void scan2(int* __restrict__ bsum, int nb) {
    if (blockIdx.x == 0 && threadIdx.x == 0) {
        int acc = 0;
        for (int i = 0; i < nb; i++) { int v = bsum[i]; bsum[i] = acc; acc += v; }
    }
}
__global__ void scan3(int* __restrict__ off, const int* __restrict__ bsum,
                      int N, int* __restrict__ cur)
{
    int gid = blockIdx.x * blockDim.x + threadIdx.x;
    if (gid < N) {
        int o = off[gid] + bsum[gid >> 10];
        off[gid] = o;
        cur[gid] = o;
    }
}
__global__ void fill_csr(const int2* __restrict__ edge, int E,
                         int* __restrict__ cur, int* __restrict__ srcarr)
{
    int e = blockIdx.x * blockDim.x + threadIdx.x;
    if (e >= E) return;
    int2 sd = edge[e];
    int slot = atomicAdd(&cur[sd.y], 1);
    srcarr[slot] = sd.x;
}

// ============================================================================
// Weight prep: transpose to [n][k] + tf32 rounding
// ============================================================================
__global__ void prep_wt0(const float* __restrict__ Wl0,
                         const float* __restrict__ Wr0, float* __restrict__ WT) {
    int i = blockIdx.x * blockDim.x + threadIdx.x;
    if (i >= 256 * 128) return;
    int n = i >> 7, k = i & 127;
    float v = (n < 128) ? Wl0[k * 128 + n] : Wr0[k * 128 + (n - 128)];
    WT[i] = __uint_as_float(f2tf32(v));
}
__global__ void prep_wt1(const float* __restrict__ Wl1,
                         const float* __restrict__ Wr1, float* __restrict__ WT) {
    int i = blockIdx.x * blockDim.x + threadIdx.x;
    if (i >= 128 * 128) return;
    int n = i >> 7, k = i & 127;
    float v = (n < 64) ? Wl1[k * 64 + n] : Wr1[k * 64 + (n - 64)];
    WT[i] = __uint_as_float(f2tf32(v));
}

// ============================================================================
// tf32 mma.sync GEMM: C[128,128] = A_tile[128,128] @ B^T  per CTA.
// BT is [n][k]; blockIdx.y selects 128-row slab of BT and output C0/C1.
// 8 warps (4x2): each warp 32x64 via 2x8 m16n8k8 fragments. BK=32, pad 36.
// ============================================================================
#define PADK 36
__global__ __launch_bounds__(256) void gemm_mma(
    const float* __restrict__ A, const float* __restrict__ BT,
    float* __restrict__ C0, float* __restrict__ C1, int nrows)
{
    __shared__ float As[128][PADK];
    __shared__ float Bs[128][PADK];

    const float* B = BT + (size_t)blockIdx.y * 128 * 128;
    float*       C = blockIdx.y ? C1 : C0;

    const int tid  = threadIdx.x;
    const int wid  = tid >> 5, lane = tid & 31;
    const int g    = lane >> 2, tig = lane & 3;      // group / thread-in-group
    const int wm   = wid >> 1,  wn  = wid & 1;       // 4 x 2 warp grid
    const int row0 = blockIdx.x * 128;

    float acc[2][8][4];
#pragma unroll
    for (int mt = 0; mt < 2; mt++)
#pragma unroll
        for (int nt = 0; nt < 8; nt++)
#pragma unroll
            for (int q = 0; q < 4; q++) acc[mt][nt][q] = 0.f;

    for (int k0 = 0; k0 < 128; k0 += 32) {
        // A chunk 128x32: 4 float4 per thread, cvt to tf32 on the way in
#pragma unroll
        for (int i = 0; i < 4; i++) {
            int f = tid + i * 256;              // 0..1023
            int r = f >> 3, c = (f & 7) << 2;   // 8 float4 per row
            float4 v = make_float4(0.f, 0.f, 0.f, 0.f);
            if (row0 + r < nrows)
                v = *(const float4*)&A[(size_t)(row0 + r) * 128 + k0 + c];
            As[r][c + 0] = __uint_as_float(f2tf32(v.x));
            As[r][c + 1] = __uint_as_float(f2tf32(v.y));
            As[r][c + 2] = __uint_as_float(f2tf32(v.z));
            As[r][c + 3] = __uint_as_float(f2tf32(v.w));
        }
        // B chunk 128x32 (already tf32-rounded)
#pragma unroll
        for (int i = 0; i < 4; i++) {
            int f = tid + i * 256;
            int r = f >> 3, c = (f & 7) << 2;
            float4 v = *(const float4*)&B[(size_t)r * 128 + k0 + c];
            *(float4*)&Bs[r][c] = v;
        }
        __syncthreads();

#pragma unroll
        for (int kk = 0; kk < 32; kk += 8) {
            uint32_t af[2][4];
#pragma unroll
            for (int mt = 0; mt < 2; mt++) {
                int r = wm * 32 + mt * 16 + g;
                af[mt][0] = __float_as_uint(As[r    ][kk + tig    ]);
                af[mt][1] = __float_as_uint(As[r + 8][kk + tig    ]);
                af[mt][2] = __float_as_uint(As[r    ][kk + tig + 4]);
                af[mt][3] = __float_as_uint(As[r + 8][kk + tig + 4]);
            }
#pragma unroll
            for (int nt = 0; nt < 8; nt++) {
                int n = wn * 64 + nt * 8 + g;
                uint32_t b0 = __float_as_uint(Bs[n][kk + tig    ]);
                uint32_t b1 = __float_as_uint(Bs[n][kk + tig + 4]);
                mma_tf32(acc[0][nt], af[0], b0, b1);
                mma_tf32(acc[1][nt], af[1], b0, b1);
            }
        }
        __syncthreads();
    }

    // epilogue: c0/c1 -> row (g), cols 2*tig, 2*tig+1; c2/c3 -> row g+8
#pragma unroll
    for (int mt = 0; mt < 2; mt++) {
        int r = row0 + wm * 32 + mt * 16 + g;
#pragma unroll
        for (int nt = 0; nt < 8; nt++) {
            int col = wn * 64 + nt * 8 + 2 * tig;
            if (r < nrows)
                *(float2*)&C[(size_t)r * 128 + col] =
                    make_float2(acc[mt][nt][0], acc[mt][nt][1]);
            if (r + 8 < nrows)
                *(float2*)&C[(size_t)(r + 8) * 128 + col] =
                    make_float2(acc[mt][nt][2], acc[mt][nt][3]);
        }
    }
}

// ============================================================================
// Fused CSR gather-reduce + combine (one warp per destination row, unroll 8)
// ============================================================================
__global__ __launch_bounds__(256) void agg_combine_relu(
    const int* __restrict__ off, const int* __restrict__ deg,
    const int* __restrict__ srcarr,
    const float* __restrict__ YL, const float* __restrict__ YR,
    const float* __restrict__ bias,
    float* __restrict__ H, int n)
{
    int warp = (blockIdx.x * 256 + threadIdx.x) >> 5;
    int lane = threadIdx.x & 31;
    if (warp >= n) return;
    int start = off[warp], len = deg[warp];
    int c = lane << 2;

    float4 acc = make_float4(0.f, 0.f, 0.f, 0.f);
    int j = 0;
    for (; j + 8 <= len; j += 8) {
        int s[8];
#pragma unroll
        for (int u = 0; u < 8; u++) s[u] = __ldg(&srcarr[start + j + u]);
        float4 v[8];
#pragma unroll
        for (int u = 0; u < 8; u++)
            v[u] = __ldg((const float4*)&YL[(size_t)s[u] * 128 + c]);
#pragma unroll
        for (int u = 0; u < 8; u++) {
            acc.x += v[u].x; acc.y += v[u].y; acc.z += v[u].z; acc.w += v[u].w;
        }
    }
    for (; j < len; j++) {
        int s = __ldg(&srcarr[start + j]);
        float4 v = __ldg((const float4*)&YL[(size_t)s * 128 + c]);
        acc.x += v.x; acc.y += v.y; acc.z += v.z; acc.w += v.w;
    }

    float inv = 1.0f / fmaxf((float)len, 1.0f);
    float4 y = *(const float4*)&YR[(size_t)warp * 128 + c];
    float4 b = *(const float4*)&bias[c];
    float4 o;
    o.x = fmaxf(fmaf(acc.x, inv, y.x + b.x), 0.f);
    o.y = fmaxf(fmaf(acc.y, inv, y.y + b.y), 0.f);
    o.z = fmaxf(fmaf(acc.z, inv, y.z + b.z), 0.f);
    o.w = fmaxf(fmaf(acc.w, inv, y.w + b.w), 0.f);
    *(float4*)&H[(size_t)warp * 128 + c] = o;
}

__global__ __launch_bounds__(256) void agg_combine_out(
    const int* __restrict__ off, const int* __restrict__ deg,
    const int* __restrict__ srcarr,
    const float* __restrict__ PQ, const float* __restrict__ bias,
    float* __restrict__ out, int n)
{
    int warp = (blockIdx.x * 256 + threadIdx.x) >> 5;
    int lane = threadIdx.x & 31;
    if (warp >= n) return;
    int start = off[warp], len = deg[warp];
    int c = lane << 1;

    float2 acc = make_float2(0.f, 0.f);
    int j = 0;
    for (; j + 8 <= len; j += 8) {
        int s[8];
#pragma unroll
        for (int u = 0; u < 8; u++) s[u] = __ldg(&srcarr[start + j + u]);
        float2 v[8];
#pragma unroll
        for (int u = 0; u < 8; u++)
            v[u] = __ldg((const float2*)&PQ[(size_t)s[u] * 128 + c]);
#pragma unroll
        for (int u = 0; u < 8; u++) { acc.x += v[u].x; acc.y += v[u].y; }
    }
    for (; j < len; j++) {
        int s = __ldg(&srcarr[start + j]);
        float2 v = __ldg((const float2*)&PQ[(size_t)s * 128 + c]);
        acc.x += v.x; acc.y += v.y;
    }

    float inv = 1.0f / fmaxf((float)len, 1.0f);
    float2 q = *(const float2*)&PQ[(size_t)warp * 128 + 64 + c];
    float2 b = *(const float2*)&bias[c];
    float2 o;
    o.x = fmaf(acc.x, inv, q.x + b.x);
    o.y = fmaf(acc.y, inv, q.y + b.y);
    *(float2*)&out[(size_t)warp * 64 + c] = o;
}

// ============================================================================
// kernel_launch — graph-capturable, allocation-free, deterministic per call.
// ============================================================================
extern "C" void kernel_launch(void* const* d_in, const int* in_sizes, int n_in,
                              void* d_out, int out_size)
{
    const float* x   = (const float*)d_in[0];
    const void*  ei  = d_in[1];
    const float* Wl0 = (const float*)d_in[2];
    const float* bl0 = (const float*)d_in[3];
    const float* Wr0 = (const float*)d_in[4];
    const float* Wl1 = (const float*)d_in[5];
    const float* bl1 = (const float*)d_in[6];
    const float* Wr1 = (const float*)d_in[7];
    float*       out = (float*)d_out;

    const int N = in_sizes[0] / 128;   // 100000
    const int E = in_sizes[1] / 2;     // 1600000

    float *YL, *YR, *H, *PQ, *WT0, *WT1;
    int2* EDGE; int *SRC, *DEG, *OFF, *CUR, *BSUM, *FLAG;
    cudaGetSymbolAddress((void**)&YL,   g_YL);
    cudaGetSymbolAddress((void**)&YR,   g_YR);
    cudaGetSymbolAddress((void**)&H,    g_H);
    cudaGetSymbolAddress((void**)&PQ,   g_PQ);
    cudaGetSymbolAddress((void**)&WT0,  g_WT0);
    cudaGetSymbolAddress((void**)&WT1,  g_WT1);
    cudaGetSymbolAddress((void**)&EDGE, g_EDGE);
    cudaGetSymbolAddress((void**)&SRC,  g_SRC);
    cudaGetSymbolAddress((void**)&DEG,  g_DEG);
    cudaGetSymbolAddress((void**)&OFF,  g_OFF);
    cudaGetSymbolAddress((void**)&CUR,  g_CUR);
    cudaGetSymbolAddress((void**)&BSUM, g_BSUM);
    cudaGetSymbolAddress((void**)&FLAG, g_FLAG);

    const int TPB = 256;
    const int nScanBlk = (N + SCAN_B - 1) / SCAN_B;

    // ---- edge preprocessing ----
    zero_int<<<(N + TPB - 1) / TPB, TPB>>>(DEG, N);
    detect_kernel<<<1, 32>>>((const int*)ei, in_sizes[1], FLAG);
    decode_edges<<<(E + TPB - 1) / TPB, TPB>>>(ei, E, N, FLAG, EDGE, DEG);

    // ---- weight prep (transpose + tf32 round) ----
    prep_wt0<<<(256 * 128 + TPB - 1) / TPB, TPB>>>(Wl0, Wr0, WT0);
    prep_wt1<<<(128 * 128 + TPB - 1) / TPB, TPB>>>(Wl1, Wr1, WT1);

    // ---- layer 0 dual GEMM: yl = x@Wl0 (y=0), yr = x@Wr0 (y=1) ----
    {
        dim3 grid((N + 127) / 128, 2);
        gemm_mma<<<grid, 256>>>(x, WT0, YL, YR, N);
    }

    // ---- CSR build ----
    scan1<<<nScanBlk, SCAN_B>>>(DEG, N, OFF, BSUM);
    scan2<<<1, 32>>>(BSUM, nScanBlk);
    scan3<<<(N + TPB - 1) / TPB, TPB>>>(OFF, BSUM, N, CUR);
    fill_csr<<<(E + TPB - 1) / TPB, TPB>>>(EDGE, E, CUR, SRC);

    // ---- layer 0 aggregation + combine + relu ----
    agg_combine_relu<<<(N * 32 + TPB - 1) / TPB, TPB>>>(
        OFF, DEG, SRC, YL, YR, bl0, H, N);

    // ---- layer 1 GEMM: pq = h @ [Wl1|Wr1] ----
    {
        dim3 grid((N + 127) / 128, 1);
        gemm_mma<<<grid, 256>>>(H, WT1, PQ, PQ, N);
    }

    // ---- layer 1 aggregation + combine -> out ----
    agg_combine_out<<<(N * 32 + TPB - 1) / TPB, TPB>>>(
        OFF, DEG, SRC, PQ, bl1, out, N);
}

// round 15
// speedup vs baseline: 2.6545x; 1.1138x over previous
#include <cuda_runtime.h>
#include <cuda_bf16.h>
#include <cstdint>

// ============================================================================
// GraphSAGE 2-layer, mean aggregation. CSR gather-reduce + tf32 mma.sync GEMMs.
// Gather-side tables (yl, p) stored bf16 to halve LTS gather traffic;
// accumulation in fp32. yr / q / h stay fp32.
//   yl(bf16), yr(f32) = x@Wl0, x@Wr0   (one launch, blockIdx.y selects)
//   h   = relu(agg(yl)/deg + yr + bl0)            (fused CSR gather)
//   p(bf16), q(f32)   = h@[Wl1|Wr1]               (split epilogue)
//   out = agg(p)/deg + q + bl1                    (fused CSR gather)
// ============================================================================

#define NMAX 100000
#define EMAX 1600000
#define SCAN_B 1024
#define NBLK ((NMAX + SCAN_B - 1) / SCAN_B)

__device__ __nv_bfloat16 g_YLB[NMAX * 128];  // bf16 gather table, layer 0
__device__ float         g_YR [NMAX * 128];
__device__ float         g_H  [NMAX * 128];
__device__ __nv_bfloat16 g_PB [NMAX * 64];   // bf16 gather table, layer 1
__device__ float         g_QB [NMAX * 64];
__device__ float         g_WT0[256 * 128];   // [n][k] tf32-rounded
__device__ float         g_WT1[128 * 128];
__device__ int2          g_EDGE[EMAX];
__device__ int           g_SRC [EMAX];
__device__ int           g_DEG [NMAX];
__device__ int           g_OFF [NMAX];
__device__ int           g_CUR [NMAX];
__device__ int           g_BSUM[NBLK];
__device__ int           g_FLAG;

__device__ __forceinline__ uint32_t f2tf32(float v) {
    uint32_t t; asm("cvt.rna.tf32.f32 %0, %1;" : "=r"(t) : "f"(v)); return t;
}
__device__ __forceinline__ void mma_tf32(float* c, const uint32_t* a,
                                         uint32_t b0, uint32_t b1) {
    asm volatile(
        "mma.sync.aligned.m16n8k8.row.col.f32.tf32.tf32.f32 "
        "{%0,%1,%2,%3}, {%4,%5,%6,%7}, {%8,%9}, {%0,%1,%2,%3};"
        : "+f"(c[0]), "+f"(c[1]), "+f"(c[2]), "+f"(c[3])
        : "r"(a[0]), "r"(a[1]), "r"(a[2]), "r"(a[3]), "r"(b0), "r"(b1));
}

// ============================================================================
// Edge preprocessing
// ============================================================================
__global__ void detect_kernel(const int* __restrict__ raw, int nwords, int* flag) {
    if (blockIdx.x == 0 && threadIdx.x == 0) {
        int is64 = 1;
        int lim = nwords < 256 ? nwords : 256;
        for (int i = 1; i < lim; i += 2)
            if (raw[i] != 0) { is64 = 0; break; }
        *flag = is64;
    }
}
__global__ void zero_int(int* __restrict__ p, int n) {
    int i = blockIdx.x * blockDim.x + threadIdx.x;
    if (i < n) p[i] = 0;
}
__global__ void decode_edges(const void* __restrict__ eiraw, int E, int N,
                             const int* __restrict__ flag,
                             int2* __restrict__ edge, int* __restrict__ deg)
{
    int e = blockIdx.x * blockDim.x + threadIdx.x;
    if (e >= E) return;
    int s, d;
    if (*flag) {
        const long long* p = (const long long*)eiraw;
        s = (int)p[e]; d = (int)p[(size_t)E + e];
    } else {
        const int* p = (const int*)eiraw;
        s = p[e]; d = p[(size_t)E + e];
    }
    s = min(max(s, 0), N - 1);
    d = min(max(d, 0), N - 1);
    edge[e] = make_int2(s, d);
    atomicAdd(&deg[d], 1);
}
__global__ __launch_bounds__(SCAN_B) void scan1(
    const int* __restrict__ deg, int N, int* __restrict__ excl, int* __restrict__ bsum)
{
    __shared__ int sh[SCAN_B];
    int gid = blockIdx.x * SCAN_B + threadIdx.x;
    int v = (gid < N) ? deg[gid] : 0;
    sh[threadIdx.x] = v;
    __syncthreads();
#pragma unroll
    for (int off = 1; off < SCAN_B; off <<= 1) {
        int t = (threadIdx.x >= off) ? sh[threadIdx.x - off] : 0;
        __syncthreads();
        sh[threadIdx.x] += t;
        __syncthreads();
    }
    if (gid < N) excl[gid] = sh[threadIdx.x] - v;
    if (threadIdx.x == SCAN_B - 1) bsum[blockIdx.x] = sh[SCAN_B - 1];
}
__global__ void scan2(int* __restrict__ bsum, int nb) {
    if (blockIdx.x == 0 && threadIdx.x == 0) {
        int acc = 0;
        for (int i = 0; i < nb; i++) { int v = bsum[i]; bsum[i] = acc; acc += v; }
    }
}
__global__ void scan3(int* __restrict__ off, const int* __restrict__ bsum,
                      int N, int* __restrict__ cur)
{
    int gid = blockIdx.x * blockDim.x + threadIdx.x;
    if (gid < N) {
        int o = off[gid] + bsum[gid >> 10];
        off[gid] = o;
        cur[gid] = o;
    }
}
__global__ void fill_csr(const int2* __restrict__ edge, int E,
                         int* __restrict__ cur, int* __restrict__ srcarr)
{
    int e = blockIdx.x * blockDim.x + threadIdx.x;
    if (e >= E) return;
    int2 sd = edge[e];
    int slot = atomicAdd(&cur[sd.y], 1);
    srcarr[slot] = sd.x;
}

// ============================================================================
// Weight prep: transpose to [n][k] + tf32 rounding
// ============================================================================
__global__ void prep_wt0(const float* __restrict__ Wl0,
                         const float* __restrict__ Wr0, float* __restrict__ WT) {
    int i = blockIdx.x * blockDim.x + threadIdx.x;
    if (i >= 256 * 128) return;
    int n = i >> 7, k = i & 127;
    float v = (n < 128) ? Wl0[k * 128 + n] : Wr0[k * 128 + (n - 128)];
    WT[i] = __uint_as_float(f2tf32(v));
}
__global__ void prep_wt1(const float* __restrict__ Wl1,
                         const float* __restrict__ Wr1, float* __restrict__ WT) {
    int i = blockIdx.x * blockDim.x + threadIdx.x;
    if (i >= 128 * 128) return;
    int n = i >> 7, k = i & 127;
    float v = (n < 64) ? Wl1[k * 64 + n] : Wr1[k * 64 + (n - 64)];
    WT[i] = __uint_as_float(f2tf32(v));
}

// ============================================================================
// tf32 mma.sync GEMM: C[128,128] = A_tile[128,128] @ B^T per CTA.
// 8 warps (4x2), warp tile 32x64 via 2x8 m16n8k8. BK=32, pad 36.
// Output modes: 0 = fp32 full 128 cols; 1 = bf16 full 128 cols;
//               2 = split (cols 0-63 -> bf16 outA[r*64+..], 64-127 -> f32 outB)
// blockIdx.y selects the 128-row BT slab + (outA/outB/mode) pair.
// ============================================================================
#define PADK 36
__global__ __launch_bounds__(256) void gemm_mma(
    const float* __restrict__ A, const float* __restrict__ BT,
    void* outA0, void* outB0, int mode0,
    void* outA1, void* outB1, int mode1, int nrows)
{
    __shared__ float As[128][PADK];
    __shared__ float Bs[128][PADK];

    const float* B   = BT + (size_t)blockIdx.y * 128 * 128;
    void* outA = blockIdx.y ? outA1 : outA0;
    void* outB = blockIdx.y ? outB1 : outB0;
    const int mode = blockIdx.y ? mode1 : mode0;

    const int tid  = threadIdx.x;
    const int wid  = tid >> 5, lane = tid & 31;
    const int g    = lane >> 2, tig = lane & 3;
    const int wm   = wid >> 1,  wn  = wid & 1;
    const int row0 = blockIdx.x * 128;

    float acc[2][8][4];
#pragma unroll
    for (int mt = 0; mt < 2; mt++)
#pragma unroll
        for (int nt = 0; nt < 8; nt++)
#pragma unroll
            for (int q = 0; q < 4; q++) acc[mt][nt][q] = 0.f;

    for (int k0 = 0; k0 < 128; k0 += 32) {
#pragma unroll
        for (int i = 0; i < 4; i++) {
            int f = tid + i * 256;
            int r = f >> 3, c = (f & 7) << 2;
            float4 v = make_float4(0.f, 0.f, 0.f, 0.f);
            if (row0 + r < nrows)
                v = *(const float4*)&A[(size_t)(row0 + r) * 128 + k0 + c];
            As[r][c + 0] = __uint_as_float(f2tf32(v.x));
            As[r][c + 1] = __uint_as_float(f2tf32(v.y));
            As[r][c + 2] = __uint_as_float(f2tf32(v.z));
            As[r][c + 3] = __uint_as_float(f2tf32(v.w));
        }
#pragma unroll
        for (int i = 0; i < 4; i++) {
            int f = tid + i * 256;
            int r = f >> 3, c = (f & 7) << 2;
            float4 v = *(const float4*)&B[(size_t)r * 128 + k0 + c];
            *(float4*)&Bs[r][c] = v;
        }
        __syncthreads();

#pragma unroll
        for (int kk = 0; kk < 32; kk += 8) {
            uint32_t af[2][4];
#pragma unroll
            for (int mt = 0; mt < 2; mt++) {
                int r = wm * 32 + mt * 16 + g;
                af[mt][0] = __float_as_uint(As[r    ][kk + tig    ]);
                af[mt][1] = __float_as_uint(As[r + 8][kk + tig    ]);
                af[mt][2] = __float_as_uint(As[r    ][kk + tig + 4]);
                af[mt][3] = __float_as_uint(As[r + 8][kk + tig + 4]);
            }
#pragma unroll
            for (int nt = 0; nt < 8; nt++) {
                int n = wn * 64 + nt * 8 + g;
                uint32_t b0 = __float_as_uint(Bs[n][kk + tig    ]);
                uint32_t b1 = __float_as_uint(Bs[n][kk + tig + 4]);
                mma_tf32(acc[0][nt], af[0], b0, b1);
                mma_tf32(acc[1][nt], af[1], b0, b1);
            }
        }
        __syncthreads();
    }

    // epilogue: fragment (mt): rows r, r+8; cols wn*64 + nt*8 + 2*tig (+1)
#pragma unroll
    for (int mt = 0; mt < 2; mt++) {
#pragma unroll
        for (int half = 0; half < 2; half++) {
            int r = row0 + wm * 32 + mt * 16 + g + half * 8;
            if (r >= nrows) continue;
#pragma unroll
            for (int nt = 0; nt < 8; nt++) {
                int col = wn * 64 + nt * 8 + 2 * tig;
                float v0 = acc[mt][nt][half * 2 + 0];
                float v1 = acc[mt][nt][half * 2 + 1];
                if (mode == 0) {
                    *(float2*)&((float*)outA)[(size_t)r * 128 + col] =
                        make_float2(v0, v1);
                } else if (mode == 1) {
                    *(__nv_bfloat162*)&((__nv_bfloat16*)outA)[(size_t)r * 128 + col] =
                        __floats2bfloat162_rn(v0, v1);
                } else {
                    if (wn == 0)
                        *(__nv_bfloat162*)&((__nv_bfloat16*)outA)[(size_t)r * 64 + col] =
                            __floats2bfloat162_rn(v0, v1);
                    else
                        *(float2*)&((float*)outB)[(size_t)r * 64 + (col - 64)] =
                            make_float2(v0, v1);
                }
            }
        }
    }
}

// ============================================================================
// Fused CSR gather-reduce + combine. bf16 gather tables, fp32 accumulate.
// ============================================================================
__global__ __launch_bounds__(256) void agg_combine_relu(
    const int* __restrict__ off, const int* __restrict__ deg,
    const int* __restrict__ srcarr,
    const __nv_bfloat16* __restrict__ YLB, const float* __restrict__ YR,
    const float* __restrict__ bias,
    float* __restrict__ H, int n)
{
    int warp = (blockIdx.x * 256 + threadIdx.x) >> 5;
    int lane = threadIdx.x & 31;
    if (warp >= n) return;
    int start = off[warp], len = deg[warp];
    int c = lane << 2;

    float4 acc = make_float4(0.f, 0.f, 0.f, 0.f);
    int j = 0;
    for (; j + 8 <= len; j += 8) {
        int s[8];
#pragma unroll
        for (int u = 0; u < 8; u++) s[u] = __ldg(&srcarr[start + j + u]);
        uint2 raw[8];
#pragma unroll
        for (int u = 0; u < 8; u++)
            raw[u] = __ldg((const uint2*)&YLB[(size_t)s[u] * 128 + c]);
#pragma unroll
        for (int u = 0; u < 8; u++) {
            float2 a = __bfloat1622float2(*(__nv_bfloat162*)&raw[u].x);
            float2 b = __bfloat1622float2(*(__nv_bfloat162*)&raw[u].y);
            acc.x += a.x; acc.y += a.y; acc.z += b.x; acc.w += b.y;
        }
    }
    for (; j < len; j++) {
        int s = __ldg(&srcarr[start + j]);
        uint2 raw = __ldg((const uint2*)&YLB[(size_t)s * 128 + c]);
        float2 a = __bfloat1622float2(*(__nv_bfloat162*)&raw.x);
        float2 b = __bfloat1622float2(*(__nv_bfloat162*)&raw.y);
        acc.x += a.x; acc.y += a.y; acc.z += b.x; acc.w += b.y;
    }

    float inv = 1.0f / fmaxf((float)len, 1.0f);
    float4 y = *(const float4*)&YR[(size_t)warp * 128 + c];
    float4 b = *(const float4*)&bias[c];
    float4 o;
    o.x = fmaxf(fmaf(acc.x, inv, y.x + b.x), 0.f);
    o.y = fmaxf(fmaf(acc.y, inv, y.y + b.y), 0.f);
    o.z = fmaxf(fmaf(acc.z, inv, y.z + b.z), 0.f);
    o.w = fmaxf(fmaf(acc.w, inv, y.w + b.w), 0.f);
    *(float4*)&H[(size_t)warp * 128 + c] = o;
}

__global__ __launch_bounds__(256) void agg_combine_out(
    const int* __restrict__ off, const int* __restrict__ deg,
    const int* __restrict__ srcarr,
    const __nv_bfloat16* __restrict__ PB, const float* __restrict__ QB,
    const float* __restrict__ bias,
    float* __restrict__ out, int n)
{
    int warp = (blockIdx.x * 256 + threadIdx.x) >> 5;
    int lane = threadIdx.x & 31;
    if (warp >= n) return;
    int start = off[warp], len = deg[warp];
    int c = lane << 1;

    float2 acc = make_float2(0.f, 0.f);
    int j = 0;
    for (; j + 8 <= len; j += 8) {
        int s[8];
#pragma unroll
        for (int u = 0; u < 8; u++) s[u] = __ldg(&srcarr[start + j + u]);
        uint32_t raw[8];
#pragma unroll
        for (int u = 0; u < 8; u++)
            raw[u] = __ldg((const uint32_t*)&PB[(size_t)s[u] * 64 + c]);
#pragma unroll
        for (int u = 0; u < 8; u++) {
            float2 v = __bfloat1622float2(*(__nv_bfloat162*)&raw[u]);
            acc.x += v.x; acc.y += v.y;
        }
    }
    for (; j < len; j++) {
        int s = __ldg(&srcarr[start + j]);
        uint32_t raw = __ldg((const uint32_t*)&PB[(size_t)s * 64 + c]);
        float2 v = __bfloat1622float2(*(__nv_bfloat162*)&raw);
        acc.x += v.x; acc.y += v.y;
    }

    float inv = 1.0f / fmaxf((float)len, 1.0f);
    float2 q = *(const float2*)&QB[(size_t)warp * 64 + c];
    float2 b = *(const float2*)&bias[c];
    float2 o;
    o.x = fmaf(acc.x, inv, q.x + b.x);
    o.y = fmaf(acc.y, inv, q.y + b.y);
    *(float2*)&out[(size_t)warp * 64 + c] = o;
}

// ============================================================================
// kernel_launch — graph-capturable, allocation-free, deterministic per call.
// ============================================================================
extern "C" void kernel_launch(void* const* d_in, const int* in_sizes, int n_in,
                              void* d_out, int out_size)
{
    const float* x   = (const float*)d_in[0];
    const void*  ei  = d_in[1];
    const float* Wl0 = (const float*)d_in[2];
    const float* bl0 = (const float*)d_in[3];
    const float* Wr0 = (const float*)d_in[4];
    const float* Wl1 = (const float*)d_in[5];
    const float* bl1 = (const float*)d_in[6];
    const float* Wr1 = (const float*)d_in[7];
    float*       out = (float*)d_out;

    const int N = in_sizes[0] / 128;   // 100000
    const int E = in_sizes[1] / 2;     // 1600000

    __nv_bfloat16 *YLB, *PB;
    float *YR, *H, *QB, *WT0, *WT1;
    int2* EDGE; int *SRC, *DEG, *OFF, *CUR, *BSUM, *FLAG;
    cudaGetSymbolAddress((void**)&YLB,  g_YLB);
    cudaGetSymbolAddress((void**)&YR,   g_YR);
    cudaGetSymbolAddress((void**)&H,    g_H);
    cudaGetSymbolAddress((void**)&PB,   g_PB);
    cudaGetSymbolAddress((void**)&QB,   g_QB);
    cudaGetSymbolAddress((void**)&WT0,  g_WT0);
    cudaGetSymbolAddress((void**)&WT1,  g_WT1);
    cudaGetSymbolAddress((void**)&EDGE, g_EDGE);
    cudaGetSymbolAddress((void**)&SRC,  g_SRC);
    cudaGetSymbolAddress((void**)&DEG,  g_DEG);
    cudaGetSymbolAddress((void**)&OFF,  g_OFF);
    cudaGetSymbolAddress((void**)&CUR,  g_CUR);
    cudaGetSymbolAddress((void**)&BSUM, g_BSUM);
    cudaGetSymbolAddress((void**)&FLAG, g_FLAG);

    const int TPB = 256;
    const int nScanBlk = (N + SCAN_B - 1) / SCAN_B;

    // ---- edge preprocessing ----
    zero_int<<<(N + TPB - 1) / TPB, TPB>>>(DEG, N);
    detect_kernel<<<1, 32>>>((const int*)ei, in_sizes[1], FLAG);
    decode_edges<<<(E + TPB - 1) / TPB, TPB>>>(ei, E, N, FLAG, EDGE, DEG);

    // ---- weight prep ----
    prep_wt0<<<(256 * 128 + TPB - 1) / TPB, TPB>>>(Wl0, Wr0, WT0);
    prep_wt1<<<(128 * 128 + TPB - 1) / TPB, TPB>>>(Wl1, Wr1, WT1);

    // ---- layer 0 dual GEMM: y=0 -> yl (bf16 full), y=1 -> yr (f32 full) ----
    {
        dim3 grid((N + 127) / 128, 2);
        gemm_mma<<<grid, 256>>>(x, WT0,
                                (void*)YLB, nullptr, 1,
                                (void*)YR,  nullptr, 0, N);
    }

    // ---- CSR build ----
    scan1<<<nScanBlk, SCAN_B>>>(DEG, N, OFF, BSUM);
    scan2<<<1, 32>>>(BSUM, nScanBlk);
    scan3<<<(N + TPB - 1) / TPB, TPB>>>(OFF, BSUM, N, CUR);
    fill_csr<<<(E + TPB - 1) / TPB, TPB>>>(EDGE, E, CUR, SRC);

    // ---- layer 0 aggregation + combine + relu ----
    agg_combine_relu<<<(N * 32 + TPB - 1) / TPB, TPB>>>(
        OFF, DEG, SRC, YLB, YR, bl0, H, N);

    // ---- layer 1 GEMM: split epilogue -> p (bf16), q (f32) ----
    {
        dim3 grid((N + 127) / 128, 1);
        gemm_mma<<<grid, 256>>>(H, WT1,
                                (void*)PB, (void*)QB, 2,
                                nullptr, nullptr, 0, N);
    }

    // ---- layer 1 aggregation + combine -> out ----
    agg_combine_out<<<(N * 32 + TPB - 1) / TPB, TPB>>>(
        OFF, DEG, SRC, PB, QB, bl1, out, N);
}